// round 4
// baseline (speedup 1.0000x reference)
#include <cuda_runtime.h>
#include <math.h>

#define NB 8
#define NH 12
#define NS 8192
#define ND 64
#define NBH (NB * NH)
#define KSEL 1024
#define NT2 512
#define PER2 (NS / NT2)   // 16

// device scratch (no allocs allowed)
__device__ float g_scores[NBH * NS];

// ---------------- Threefry-2x32 (JAX), key = (0, 42) ----------------
__device__ __forceinline__ unsigned rotl32(unsigned x, int r) {
    return __funnelshift_l(x, x, r);
}

__device__ __forceinline__ void threefry2x32_0_42(unsigned c0, unsigned c1,
                                                  unsigned& o0, unsigned& o1) {
    const unsigned ks0 = 0u;
    const unsigned ks1 = 42u;
    const unsigned ks2 = 0x1BD11BDAu ^ 0u ^ 42u;
    unsigned x0 = c0 + ks0;
    unsigned x1 = c1 + ks1;
#define TF_R(r) { x0 += x1; x1 = rotl32(x1, (r)); x1 ^= x0; }
    TF_R(13) TF_R(15) TF_R(26) TF_R(6)
    x0 += ks1; x1 += ks2 + 1u;
    TF_R(17) TF_R(29) TF_R(16) TF_R(24)
    x0 += ks2; x1 += ks0 + 2u;
    TF_R(13) TF_R(15) TF_R(26) TF_R(6)
    x0 += ks0; x1 += ks1 + 3u;
    TF_R(17) TF_R(29) TF_R(16) TF_R(24)
    x0 += ks1; x1 += ks2 + 4u;
    TF_R(13) TF_R(15) TF_R(26) TF_R(6)
    x0 += ks2; x1 += ks0 + 5u;
#undef TF_R
    o0 = x0; o1 = x1;
}

// ---------------- accurate fp32 exp/log (fast-math immune, ~1 ulp) ----------------
__device__ __forceinline__ float f_exp(float x) {
    float n = rintf(x * 1.4426950408889634f);
    float r = __fmaf_rn(n, -0.693359375f, x);
    r = __fmaf_rn(n, 2.12194440e-4f, r);
    float p = 1.9841270e-4f;                  // 1/5040
    p = __fmaf_rn(p, r, 1.3888889e-3f);       // 1/720
    p = __fmaf_rn(p, r, 8.3333333e-3f);       // 1/120
    p = __fmaf_rn(p, r, 4.1666668e-2f);       // 1/24
    p = __fmaf_rn(p, r, 1.6666667e-1f);       // 1/6
    p = __fmaf_rn(p, r, 0.5f);                // 1/2
    float e = __fmaf_rn(p, r * r, r) + 1.0f;
    int ni = (int)n;
    ni = max(-126, min(127, ni));
    e *= __uint_as_float((unsigned)(ni + 127) << 23);
    return e;
}

__device__ __forceinline__ float f_log(float x) {
    // x: positive, normal
    unsigned u = __float_as_uint(x);
    int e = (int)(u >> 23) - 127;
    float m = __uint_as_float((u & 0x007fffffu) | 0x3f800000u);  // [1,2)
    if (m > 1.4142135f) { m = m * 0.5f; e += 1; }                // [0.7071,1.4142]
    float fe = (float)e;
    float s = __fdiv_rn(m - 1.0f, m + 1.0f);
    float s2 = s * s;
    float p = 0.11111111f;               // 1/9
    p = __fmaf_rn(p, s2, 0.14285715f);   // 1/7
    p = __fmaf_rn(p, s2, 0.2f);          // 1/5
    p = __fmaf_rn(p, s2, 0.33333334f);   // 1/3
    float w = s + s;
    float lm = __fmaf_rn(w * s2, p, w);  // log(m) = 2s + 2s*s2*P(s2)
    float r = __fmaf_rn(fe, -2.12194440e-4f, lm);
    r = __fmaf_rn(fe, 0.693359375f, r);
    return r;
}

// ---------------- JAX gumbel(key=42) at flat index i ----------------
// PARTITIONABLE threefry scheme (jax >= 0.4.30 default):
//   counts = iota(uint64); counter = (hi32, lo32) = (0, i) for i < 2^32
//   32-bit draw = out0 ^ out1
__device__ __forceinline__ float gumbel_at(unsigned i) {
    unsigned o0, o1;
    threefry2x32_0_42(0u, i, o0, o1);
    unsigned bits = o0 ^ o1;
    float f = __uint_as_float((bits >> 9) | 0x3f800000u) - 1.0f;   // [0,1)
    const float tiny = 1.17549435e-38f;
    float uu = f * (1.0f - tiny) + tiny;
    uu = fmaxf(tiny, uu);
    return -f_log(-f_log(uu));
}

// monotone float -> sortable uint
__device__ __forceinline__ unsigned f2k(float v) {
    unsigned u = __float_as_uint(v);
    return (u & 0x80000000u) ? ~u : (u | 0x80000000u);
}

// ---------------- kernel 1: scores = q0 . k / 8 ----------------
__global__ void __launch_bounds__(256) score_kernel(const float* __restrict__ q,
                                                    const float* __restrict__ k) {
    int bh = blockIdx.y;
    __shared__ float qs[ND];
    if (threadIdx.x < ND)
        qs[threadIdx.x] = q[(size_t)bh * NS * ND + threadIdx.x];
    __syncthreads();

    int base = blockIdx.x * 1024;
    const float4* qv4 = (const float4*)qs;
    for (int r = threadIdx.x; r < 1024; r += 256) {
        int s = base + r;
        const float4* kr = (const float4*)(k + ((size_t)bh * NS + s) * ND);
        float4 acc = make_float4(0.f, 0.f, 0.f, 0.f);
#pragma unroll
        for (int j = 0; j < 16; ++j) {
            float4 kv = kr[j];
            float4 qv = qv4[j];
            acc.x = __fmaf_rn(qv.x, kv.x, acc.x);
            acc.y = __fmaf_rn(qv.y, kv.y, acc.y);
            acc.z = __fmaf_rn(qv.z, kv.z, acc.z);
            acc.w = __fmaf_rn(qv.w, kv.w, acc.w);
        }
        float dot = (acc.x + acc.y) + (acc.z + acc.w);
        g_scores[bh * NS + s] = dot * 0.125f;   // /8 exact
    }
}

// ---------------- kernel 2: softmax probs + gumbel + radix top-k + scatter ----------------
__global__ void __launch_bounds__(NT2) select_kernel(const float* __restrict__ token_mask,
                                                     float* __restrict__ out) {
    int bh = blockIdx.x;
    int b = bh / NH;
    int tid = threadIdx.x;
    int lane = tid & 31, wid = tid >> 5;

    __shared__ float shv_f[NS];          // 32 KB, reused as keys
    __shared__ unsigned hist[256];
    __shared__ float red_f[16];
    __shared__ double red_d[16];
    __shared__ float sh_max;
    __shared__ float sh_denom;
    __shared__ int sh_bin;
    __shared__ unsigned sh_cum, sh_eq;
    unsigned* shv_u = (unsigned*)shv_f;

    const float* sc = g_scores + bh * NS;

    // pass A: load scores + block max
    float le[PER2];
    float mx = -3.402823466e38f;
#pragma unroll
    for (int it = 0; it < PER2; ++it) {
        int s = tid + it * NT2;
        float v = sc[s];
        le[it] = v;
        mx = fmaxf(mx, v);
    }
    for (int o = 16; o; o >>= 1) mx = fmaxf(mx, __shfl_xor_sync(0xffffffffu, mx, o));
    if (lane == 0) red_f[wid] = mx;
    __syncthreads();
    if (tid == 0) {
        float m = red_f[0];
        for (int i = 1; i < 16; ++i) m = fmaxf(m, red_f[i]);
        sh_max = m;
    }
    __syncthreads();
    mx = sh_max;

    // pass B: e = exp(score - max) * mask; double sum (fixed order, deterministic)
    double lsum = 0.0;
#pragma unroll
    for (int it = 0; it < PER2; ++it) {
        int s = tid + it * NT2;
        float e = f_exp(le[it] - mx) * token_mask[b * NS + s];
        le[it] = e;
        lsum += (double)e;
    }
    for (int o = 16; o; o >>= 1) lsum += __shfl_xor_sync(0xffffffffu, lsum, o);
    if (lane == 0) red_d[wid] = lsum;
    __syncthreads();
    if (tid == 0) {
        double t = 0.0;
        for (int i = 0; i < 16; ++i) t += red_d[i];
        sh_denom = (float)t + 1e-6f;
    }
    __syncthreads();
    float denom = sh_denom;

    // pass C: value = log((e + eps/S)/denom) + gumbel ; sortable keys
    const float C1 = (float)(1e-6 / 8192.0);
    unsigned lk[PER2];
#pragma unroll
    for (int it = 0; it < PER2; ++it) {
        int s = tid + it * NT2;
        float att = __fdiv_rn(__fadd_rn(le[it], C1), denom);
        float v = __fadd_rn(f_log(att), gumbel_at((unsigned)(bh * NS + s)));
        unsigned kk = f2k(v);
        lk[it] = kk;
        shv_u[s] = kk;
    }
    __syncthreads();

    // radix select: threshold key of the KSEL-th largest (ties -> lowest index)
    unsigned prefix = 0, hmask = 0, remain = KSEL, eqTotal = 0;
    for (int byte = 3; byte >= 0; --byte) {
        for (int i = tid; i < 256; i += NT2) hist[i] = 0;
        __syncthreads();
        int sh = byte * 8;
#pragma unroll
        for (int it = 0; it < PER2; ++it) {
            unsigned kk = lk[it];
            if ((kk & hmask) == prefix) atomicAdd(&hist[(kk >> sh) & 0xffu], 1u);
        }
        __syncthreads();
        if (tid == 0) {
            unsigned cum = 0;
            int bin = 255;
            for (; bin > 0; --bin) {
                unsigned c = hist[bin];
                if (cum + c >= remain) break;
                cum += c;
            }
            sh_bin = bin; sh_cum = cum; sh_eq = hist[bin];
        }
        __syncthreads();
        prefix |= ((unsigned)sh_bin) << sh;
        hmask  |= 0xffu << sh;
        remain -= sh_cum;
        eqTotal = sh_eq;
        __syncthreads();
    }
    unsigned thresh = prefix;
    unsigned need = remain;   // # of keys == thresh to include (lowest indices first)

    // pass D: write boolean output AS FLOAT (harness promotes bool -> float32).
    // out[bh, p]: p==0 forced true; p>=1 true iff sampled index s=p-1 is in
    // top-k (index 8191 -> pos 8192 dropped).
#pragma unroll
    for (int it = 0; it < PER2; ++it) {
        int p = tid + it * NT2;
        float o;
        if (p == 0) {
            o = 1.0f;
        } else {
            int s = p - 1;
            unsigned kk = shv_u[s];
            if (kk > thresh) {
                o = 1.0f;
            } else if (kk == thresh) {
                if (eqTotal == need) {
                    o = 1.0f;
                } else {
                    unsigned rank = 0;
                    for (int j = 0; j < s; ++j) rank += (shv_u[j] == thresh);
                    o = (rank < need) ? 1.0f : 0.0f;
                }
            } else {
                o = 0.0f;
            }
        }
        out[bh * NS + p] = o;
    }
}

extern "C" void kernel_launch(void* const* d_in, const int* in_sizes, int n_in,
                              void* d_out, int out_size) {
    const float* q = (const float*)d_in[0];
    const float* k = (const float*)d_in[1];
    // d_in[2] = v : unused by the reference computation
    const float* token_mask = (const float*)d_in[3];

    score_kernel<<<dim3(8, NBH), 256>>>(q, k);
    select_kernel<<<NBH, NT2>>>(token_mask, (float*)d_out);
}

// round 5
// speedup vs baseline: 1.5889x; 1.5889x over previous
#include <cuda_runtime.h>
#include <math.h>

#define NB 8
#define NH 12
#define NS 8192
#define ND 64
#define NBH (NB * NH)
#define KSEL 1024
#define NT2 1024
#define PER2 (NS / NT2)   // 8
#define RT 128            // rows per score tile

// device scratch (no allocs allowed)
__device__ float g_scores[NBH * NS];

// ---------------- Threefry-2x32 (JAX), key = (0, 42) ----------------
__device__ __forceinline__ unsigned rotl32(unsigned x, int r) {
    return __funnelshift_l(x, x, r);
}

__device__ __forceinline__ void threefry2x32_0_42(unsigned c0, unsigned c1,
                                                  unsigned& o0, unsigned& o1) {
    const unsigned ks0 = 0u;
    const unsigned ks1 = 42u;
    const unsigned ks2 = 0x1BD11BDAu ^ 0u ^ 42u;
    unsigned x0 = c0 + ks0;
    unsigned x1 = c1 + ks1;
#define TF_R(r) { x0 += x1; x1 = rotl32(x1, (r)); x1 ^= x0; }
    TF_R(13) TF_R(15) TF_R(26) TF_R(6)
    x0 += ks1; x1 += ks2 + 1u;
    TF_R(17) TF_R(29) TF_R(16) TF_R(24)
    x0 += ks2; x1 += ks0 + 2u;
    TF_R(13) TF_R(15) TF_R(26) TF_R(6)
    x0 += ks0; x1 += ks1 + 3u;
    TF_R(17) TF_R(29) TF_R(16) TF_R(24)
    x0 += ks1; x1 += ks2 + 4u;
    TF_R(13) TF_R(15) TF_R(26) TF_R(6)
    x0 += ks2; x1 += ks0 + 5u;
#undef TF_R
    o0 = x0; o1 = x1;
}

// ---------------- accurate fp32 exp/log (fast-math immune, ~1 ulp) ----------------
__device__ __forceinline__ float f_exp(float x) {
    float n = rintf(x * 1.4426950408889634f);
    float r = __fmaf_rn(n, -0.693359375f, x);
    r = __fmaf_rn(n, 2.12194440e-4f, r);
    float p = 1.9841270e-4f;
    p = __fmaf_rn(p, r, 1.3888889e-3f);
    p = __fmaf_rn(p, r, 8.3333333e-3f);
    p = __fmaf_rn(p, r, 4.1666668e-2f);
    p = __fmaf_rn(p, r, 1.6666667e-1f);
    p = __fmaf_rn(p, r, 0.5f);
    float e = __fmaf_rn(p, r * r, r) + 1.0f;
    int ni = (int)n;
    ni = max(-126, min(127, ni));
    e *= __uint_as_float((unsigned)(ni + 127) << 23);
    return e;
}

__device__ __forceinline__ float f_log(float x) {
    unsigned u = __float_as_uint(x);
    int e = (int)(u >> 23) - 127;
    float m = __uint_as_float((u & 0x007fffffu) | 0x3f800000u);
    if (m > 1.4142135f) { m = m * 0.5f; e += 1; }
    float fe = (float)e;
    float s = __fdiv_rn(m - 1.0f, m + 1.0f);
    float s2 = s * s;
    float p = 0.11111111f;
    p = __fmaf_rn(p, s2, 0.14285715f);
    p = __fmaf_rn(p, s2, 0.2f);
    p = __fmaf_rn(p, s2, 0.33333334f);
    float w = s + s;
    float lm = __fmaf_rn(w * s2, p, w);
    float r = __fmaf_rn(fe, -2.12194440e-4f, lm);
    r = __fmaf_rn(fe, 0.693359375f, r);
    return r;
}

// ---------------- JAX gumbel(key=42) at flat index i ----------------
// PARTITIONABLE threefry: 32-bit draw = out0 ^ out1 of threefry(key, (0, i))
__device__ __forceinline__ float gumbel_at(unsigned i) {
    unsigned o0, o1;
    threefry2x32_0_42(0u, i, o0, o1);
    unsigned bits = o0 ^ o1;
    float f = __uint_as_float((bits >> 9) | 0x3f800000u) - 1.0f;   // [0,1)
    const float tiny = 1.17549435e-38f;
    float uu = f * (1.0f - tiny) + tiny;
    uu = fmaxf(tiny, uu);
    return -f_log(-f_log(uu));
}

// monotone float -> sortable uint
__device__ __forceinline__ unsigned f2k(float v) {
    unsigned u = __float_as_uint(v);
    return (u & 0x80000000u) ? ~u : (u | 0x80000000u);
}

// ---------------- kernel 1: scores = q0 . k / 8 (smem-staged, coalesced) ----------------
// Per-row arithmetic is bit-identical to R4: same fma chains into acc.{x,y,z,w},
// same (x+y)+(z+w) combine, *0.125f. Only the memory path changed.
__global__ void __launch_bounds__(RT) score_kernel(const float* __restrict__ q,
                                                   const float* __restrict__ k) {
    __shared__ float4 sk[RT * 17];   // odd stride: conflict-free LDS.128
    __shared__ float4 qs4[16];

    int tile = blockIdx.x;                 // 6144 tiles
    int bh = tile >> 6;                    // 64 tiles of 128 rows per bh
    int row0 = (tile & 63) * RT;

    if (threadIdx.x < 16)
        qs4[threadIdx.x] = ((const float4*)(q + (size_t)bh * NS * ND))[threadIdx.x];

    // coalesced tile load: 128 rows x 16 float4 = 2048 float4, 128 threads x 16
    const float4* kg = (const float4*)(k + ((size_t)bh * NS + row0) * ND);
#pragma unroll
    for (int i = 0; i < 16; ++i) {
        int L = i * RT + threadIdx.x;      // warp-contiguous
        sk[(L >> 4) * 17 + (L & 15)] = kg[L];
    }
    __syncthreads();

    int t = threadIdx.x;
    float4 acc = make_float4(0.f, 0.f, 0.f, 0.f);
#pragma unroll
    for (int j = 0; j < 16; ++j) {
        float4 kv = sk[t * 17 + j];
        float4 qv = qs4[j];
        acc.x = __fmaf_rn(qv.x, kv.x, acc.x);
        acc.y = __fmaf_rn(qv.y, kv.y, acc.y);
        acc.z = __fmaf_rn(qv.z, kv.z, acc.z);
        acc.w = __fmaf_rn(qv.w, kv.w, acc.w);
    }
    float dot = (acc.x + acc.y) + (acc.z + acc.w);
    g_scores[bh * NS + row0 + t] = dot * 0.125f;
}

// ---------------- kernel 2: softmax probs + gumbel + radix top-k + scatter ----------------
__global__ void __launch_bounds__(NT2) select_kernel(const float* __restrict__ token_mask,
                                                     float* __restrict__ out) {
    int bh = blockIdx.x;
    int b = bh / NH;
    int tid = threadIdx.x;
    int lane = tid & 31, wid = tid >> 5;

    __shared__ float shv_f[NS];          // 32 KB, reused as keys
    __shared__ unsigned hist[256];
    __shared__ float red_f[32];
    __shared__ double red_d[32];
    __shared__ float sh_max;
    __shared__ float sh_denom;
    __shared__ int sh_bin;
    __shared__ unsigned sh_cum, sh_eq;
    unsigned* shv_u = (unsigned*)shv_f;

    const float* sc = g_scores + bh * NS;

    // pass A: load scores + block max
    float le[PER2];
    float mx = -3.402823466e38f;
#pragma unroll
    for (int it = 0; it < PER2; ++it) {
        int s = tid + it * NT2;
        float v = sc[s];
        le[it] = v;
        mx = fmaxf(mx, v);
    }
    for (int o = 16; o; o >>= 1) mx = fmaxf(mx, __shfl_xor_sync(0xffffffffu, mx, o));
    if (lane == 0) red_f[wid] = mx;
    __syncthreads();
    if (wid == 0) {
        float m = red_f[lane];
        for (int o = 16; o; o >>= 1) m = fmaxf(m, __shfl_xor_sync(0xffffffffu, m, o));
        if (lane == 0) sh_max = m;
    }
    __syncthreads();
    mx = sh_max;

    // pass B: e = exp(score - max) * mask; double sum (rounded once -> order-safe)
    double lsum = 0.0;
#pragma unroll
    for (int it = 0; it < PER2; ++it) {
        int s = tid + it * NT2;
        float e = f_exp(le[it] - mx) * token_mask[b * NS + s];
        le[it] = e;
        lsum += (double)e;
    }
    for (int o = 16; o; o >>= 1) lsum += __shfl_xor_sync(0xffffffffu, lsum, o);
    if (lane == 0) red_d[wid] = lsum;
    __syncthreads();
    if (wid == 0) {
        double t = red_d[lane];
        for (int o = 16; o; o >>= 1) t += __shfl_xor_sync(0xffffffffu, t, o);
        if (lane == 0) sh_denom = (float)t + 1e-6f;
    }
    __syncthreads();
    float denom = sh_denom;

    // pass C: value = log((e + eps/S)/denom) + gumbel ; sortable keys
    const float C1 = (float)(1e-6 / 8192.0);
    unsigned lk[PER2];
#pragma unroll
    for (int it = 0; it < PER2; ++it) {
        int s = tid + it * NT2;
        float att = __fdiv_rn(__fadd_rn(le[it], C1), denom);
        float v = __fadd_rn(f_log(att), gumbel_at((unsigned)(bh * NS + s)));
        unsigned kk = f2k(v);
        lk[it] = kk;
        shv_u[s] = kk;
    }
    __syncthreads();

    // radix select: threshold key of the KSEL-th largest (ties -> lowest index)
    unsigned prefix = 0, hmask = 0, remain = KSEL, eqTotal = 0;
    for (int byte = 3; byte >= 0; --byte) {
        if (tid < 256) hist[tid] = 0;
        __syncthreads();
        int sh = byte * 8;
#pragma unroll
        for (int it = 0; it < PER2; ++it) {
            unsigned kk = lk[it];
            if ((kk & hmask) == prefix) atomicAdd(&hist[(kk >> sh) & 0xffu], 1u);
        }
        __syncthreads();
        // warp-parallel reverse scan over 256 bins (warp 0)
        if (wid == 0) {
            unsigned cnt[8];
            unsigned ssum = 0;
#pragma unroll
            for (int qq = 0; qq < 8; ++qq) { cnt[qq] = hist[lane * 8 + qq]; ssum += cnt[qq]; }
            // inclusive suffix sum across lanes (from lane 31 downward)
            unsigned x = ssum;
#pragma unroll
            for (int off = 1; off < 32; off <<= 1) {
                unsigned y = __shfl_down_sync(0xffffffffu, x, off);
                if (lane + off < 32) x += y;
            }
            unsigned excl = x - ssum;     // keys in bins strictly above this lane's group
            bool hit = (excl < remain) && (x >= remain);
            unsigned hmsk = __ballot_sync(0xffffffffu, hit);
            int hl = __ffs(hmsk) - 1;
            if (lane == hl) {
                unsigned cum = excl;
                int bq = 7;
                for (; bq > 0; --bq) {
                    if (cum + cnt[bq] >= remain) break;
                    cum += cnt[bq];
                }
                sh_bin = lane * 8 + bq;
                sh_cum = cum;
                sh_eq = cnt[bq];
            }
        }
        __syncthreads();
        prefix |= ((unsigned)sh_bin) << sh;
        hmask  |= 0xffu << sh;
        remain -= sh_cum;
        eqTotal = sh_eq;
        __syncthreads();
    }
    unsigned thresh = prefix;
    unsigned need = remain;   // # of keys == thresh to include (lowest indices first)

    // pass D: write boolean output AS FLOAT.
    // out[bh, p]: p==0 forced true; p>=1 true iff sampled index s=p-1 is in
    // top-k (index 8191 -> pos 8192 dropped).
#pragma unroll
    for (int it = 0; it < PER2; ++it) {
        int p = tid + it * NT2;
        float o;
        if (p == 0) {
            o = 1.0f;
        } else {
            int s = p - 1;
            unsigned kk = shv_u[s];
            if (kk > thresh) {
                o = 1.0f;
            } else if (kk == thresh) {
                if (eqTotal == need) {
                    o = 1.0f;
                } else {
                    unsigned rank = 0;
                    for (int j = 0; j < s; ++j) rank += (shv_u[j] == thresh);
                    o = (rank < need) ? 1.0f : 0.0f;
                }
            } else {
                o = 0.0f;
            }
        }
        out[bh * NS + p] = o;
    }
}

extern "C" void kernel_launch(void* const* d_in, const int* in_sizes, int n_in,
                              void* d_out, int out_size) {
    const float* q = (const float*)d_in[0];
    const float* k = (const float*)d_in[1];
    // d_in[2] = v : unused by the reference computation
    const float* token_mask = (const float*)d_in[3];

    score_kernel<<<NBH * (NS / RT), RT>>>(q, k);
    select_kernel<<<NBH, NT2>>>(token_mask, (float*)d_out);
}

// round 6
// speedup vs baseline: 1.6763x; 1.0550x over previous
#include <cuda_runtime.h>
#include <math.h>

#define NB 8
#define NH 12
#define NS 8192
#define ND 64
#define NBH (NB * NH)
#define KSEL 1024
#define NT2 1024
#define PER2 (NS / NT2)   // 8
#define RT 128            // rows per score tile
#define TILES_PER_CTA 8
#define SCTA (NBH * (NS / RT) / TILES_PER_CTA)   // 768

// device scratch (no allocs allowed)
__device__ float g_scores[NBH * NS];
__device__ float g_gumbel[NBH * NS];
__device__ unsigned g_maxenc[NBH];

// ---------------- Threefry-2x32 (JAX), key = (0, 42) ----------------
__device__ __forceinline__ unsigned rotl32(unsigned x, int r) {
    return __funnelshift_l(x, x, r);
}

__device__ __forceinline__ void threefry2x32_0_42(unsigned c0, unsigned c1,
                                                  unsigned& o0, unsigned& o1) {
    const unsigned ks0 = 0u;
    const unsigned ks1 = 42u;
    const unsigned ks2 = 0x1BD11BDAu ^ 0u ^ 42u;
    unsigned x0 = c0 + ks0;
    unsigned x1 = c1 + ks1;
#define TF_R(r) { x0 += x1; x1 = rotl32(x1, (r)); x1 ^= x0; }
    TF_R(13) TF_R(15) TF_R(26) TF_R(6)
    x0 += ks1; x1 += ks2 + 1u;
    TF_R(17) TF_R(29) TF_R(16) TF_R(24)
    x0 += ks2; x1 += ks0 + 2u;
    TF_R(13) TF_R(15) TF_R(26) TF_R(6)
    x0 += ks0; x1 += ks1 + 3u;
    TF_R(17) TF_R(29) TF_R(16) TF_R(24)
    x0 += ks1; x1 += ks2 + 4u;
    TF_R(13) TF_R(15) TF_R(26) TF_R(6)
    x0 += ks2; x1 += ks0 + 5u;
#undef TF_R
    o0 = x0; o1 = x1;
}

// ---------------- accurate fp32 exp/log (fast-math immune, ~1 ulp) ----------------
__device__ __forceinline__ float f_exp(float x) {
    float n = rintf(x * 1.4426950408889634f);
    float r = __fmaf_rn(n, -0.693359375f, x);
    r = __fmaf_rn(n, 2.12194440e-4f, r);
    float p = 1.9841270e-4f;
    p = __fmaf_rn(p, r, 1.3888889e-3f);
    p = __fmaf_rn(p, r, 8.3333333e-3f);
    p = __fmaf_rn(p, r, 4.1666668e-2f);
    p = __fmaf_rn(p, r, 1.6666667e-1f);
    p = __fmaf_rn(p, r, 0.5f);
    float e = __fmaf_rn(p, r * r, r) + 1.0f;
    int ni = (int)n;
    ni = max(-126, min(127, ni));
    e *= __uint_as_float((unsigned)(ni + 127) << 23);
    return e;
}

__device__ __forceinline__ float f_log(float x) {
    unsigned u = __float_as_uint(x);
    int e = (int)(u >> 23) - 127;
    float m = __uint_as_float((u & 0x007fffffu) | 0x3f800000u);
    if (m > 1.4142135f) { m = m * 0.5f; e += 1; }
    float fe = (float)e;
    float s = __fdiv_rn(m - 1.0f, m + 1.0f);
    float s2 = s * s;
    float p = 0.11111111f;
    p = __fmaf_rn(p, s2, 0.14285715f);
    p = __fmaf_rn(p, s2, 0.2f);
    p = __fmaf_rn(p, s2, 0.33333334f);
    float w = s + s;
    float lm = __fmaf_rn(w * s2, p, w);
    float r = __fmaf_rn(fe, -2.12194440e-4f, lm);
    r = __fmaf_rn(fe, 0.693359375f, r);
    return r;
}

// ---------------- JAX gumbel(key=42) at flat index i ----------------
// PARTITIONABLE threefry: 32-bit draw = out0 ^ out1 of threefry(key, (0, i))
__device__ __forceinline__ float gumbel_at(unsigned i) {
    unsigned o0, o1;
    threefry2x32_0_42(0u, i, o0, o1);
    unsigned bits = o0 ^ o1;
    float f = __uint_as_float((bits >> 9) | 0x3f800000u) - 1.0f;   // [0,1)
    const float tiny = 1.17549435e-38f;
    float uu = f * (1.0f - tiny) + tiny;
    uu = fmaxf(tiny, uu);
    return -f_log(-f_log(uu));
}

// monotone float -> sortable uint (and inverse)
__device__ __forceinline__ unsigned f2k(float v) {
    unsigned u = __float_as_uint(v);
    return (u & 0x80000000u) ? ~u : (u | 0x80000000u);
}
__device__ __forceinline__ float k2f(unsigned k) {
    return (k & 0x80000000u) ? __uint_as_float(k & 0x7fffffffu)
                             : __uint_as_float(~k);
}

// ---------------- kernel 0: reset per-bh max ----------------
__global__ void init_kernel() {
    if (threadIdx.x < NBH) g_maxenc[threadIdx.x] = 0u;   // below any encoded float
}

// ---------------- kernel 1: persistent scores + gumbel + per-bh max ----------------
// Per-row arithmetic bit-identical to R5. Gumbel computed here (hidden under
// the DRAM stream). Per-bh max via exact encoded atomicMax (order-free).
__global__ void __launch_bounds__(RT) score_kernel(const float* __restrict__ q,
                                                   const float* __restrict__ k) {
    __shared__ float4 sk[RT * 17];   // odd stride: conflict-free LDS.128
    __shared__ float4 qs4[16];
    __shared__ unsigned redmax[4];

    int t = threadIdx.x;
    int bh = blockIdx.x >> 3;                       // 8 CTAs per bh
    int row_base0 = (blockIdx.x & 7) * (TILES_PER_CTA * RT);  // 1024 rows per CTA

    if (t < 16)
        qs4[t] = ((const float4*)(q + (size_t)bh * NS * ND))[t];

    const float4* kg = (const float4*)(k + ((size_t)bh * NS + row_base0) * ND);

    // prologue: prefetch tile 0 into registers
    float4 stage[16];
#pragma unroll
    for (int i = 0; i < 16; ++i) stage[i] = kg[i * RT + t];

    float cmax = -3.402823466e38f;

    for (int it = 0; it < TILES_PER_CTA; ++it) {
        // commit staged tile to smem
#pragma unroll
        for (int i = 0; i < 16; ++i) {
            int L = i * RT + t;
            sk[(L >> 4) * 17 + (L & 15)] = stage[i];
        }
        __syncthreads();

        // prefetch next tile (LDGs in flight while we compute)
        if (it + 1 < TILES_PER_CTA) {
            const float4* kgn = kg + (it + 1) * (RT * 16);
#pragma unroll
            for (int i = 0; i < 16; ++i) stage[i] = kgn[i * RT + t];
        }

        // compute this tile: thread t owns row (row_base0 + it*RT + t)
        float4 acc = make_float4(0.f, 0.f, 0.f, 0.f);
#pragma unroll
        for (int j = 0; j < 16; ++j) {
            float4 kv = sk[t * 17 + j];
            float4 qv = qs4[j];
            acc.x = __fmaf_rn(qv.x, kv.x, acc.x);
            acc.y = __fmaf_rn(qv.y, kv.y, acc.y);
            acc.z = __fmaf_rn(qv.z, kv.z, acc.z);
            acc.w = __fmaf_rn(qv.w, kv.w, acc.w);
        }
        float dot = ((acc.x + acc.y) + (acc.z + acc.w)) * 0.125f;
        int srow = row_base0 + it * RT + t;
        int flat = bh * NS + srow;
        g_scores[flat] = dot;
        cmax = fmaxf(cmax, dot);
        g_gumbel[flat] = gumbel_at((unsigned)flat);   // ALU work hidden under DRAM

        __syncthreads();   // all reads of sk done before next overwrite
    }

    // CTA max -> global encoded atomicMax (exact, order-free)
    for (int o = 16; o; o >>= 1) cmax = fmaxf(cmax, __shfl_xor_sync(0xffffffffu, cmax, o));
    if ((t & 31) == 0) redmax[t >> 5] = f2k(cmax);
    __syncthreads();
    if (t == 0) {
        unsigned m = redmax[0];
        m = max(m, redmax[1]); m = max(m, redmax[2]); m = max(m, redmax[3]);
        atomicMax(&g_maxenc[bh], m);
    }
}

// ---------------- kernel 2: softmax probs + gumbel add + radix top-k + scatter ----------------
__global__ void __launch_bounds__(NT2) select_kernel(const float* __restrict__ token_mask,
                                                     float* __restrict__ out) {
    int bh = blockIdx.x;
    int b = bh / NH;
    int tid = threadIdx.x;
    int lane = tid & 31, wid = tid >> 5;

    __shared__ float shv_f[NS];          // 32 KB, sortable keys
    __shared__ unsigned hist[256];
    __shared__ double red_d[32];
    __shared__ float sh_denom;
    __shared__ int sh_bin;
    __shared__ unsigned sh_cum, sh_eq;
    unsigned* shv_u = (unsigned*)shv_f;

    const float* sc = g_scores + bh * NS;
    const float* gu = g_gumbel + bh * NS;

    float mx = k2f(g_maxenc[bh]);        // exact row max from kernel 1

    // pass A/B fused: e = exp(score - max) * mask; double sum (rounded once)
    float le[PER2];
    double lsum = 0.0;
#pragma unroll
    for (int it = 0; it < PER2; ++it) {
        int s = tid + it * NT2;
        float e = f_exp(sc[s] - mx) * token_mask[b * NS + s];
        le[it] = e;
        lsum += (double)e;
    }
    for (int o = 16; o; o >>= 1) lsum += __shfl_xor_sync(0xffffffffu, lsum, o);
    if (lane == 0) red_d[wid] = lsum;
    __syncthreads();
    if (wid == 0) {
        double tt = red_d[lane];
        for (int o = 16; o; o >>= 1) tt += __shfl_xor_sync(0xffffffffu, tt, o);
        if (lane == 0) sh_denom = (float)tt + 1e-6f;
    }
    __syncthreads();
    float denom = sh_denom;

    // pass C: value = log((e + eps/S)/denom) + gumbel ; sortable keys
    const float C1 = (float)(1e-6 / 8192.0);
    unsigned lk[PER2];
#pragma unroll
    for (int it = 0; it < PER2; ++it) {
        int s = tid + it * NT2;
        float att = __fdiv_rn(__fadd_rn(le[it], C1), denom);
        float v = __fadd_rn(f_log(att), gu[s]);
        unsigned kk = f2k(v);
        lk[it] = kk;
        shv_u[s] = kk;
    }
    __syncthreads();

    // radix select: threshold key of the KSEL-th largest (ties -> lowest index)
    unsigned prefix = 0, hmask = 0, remain = KSEL, eqTotal = 0;
    for (int byte = 3; byte >= 0; --byte) {
        if (tid < 256) hist[tid] = 0;
        __syncthreads();
        int sh = byte * 8;
#pragma unroll
        for (int it = 0; it < PER2; ++it) {
            unsigned kk = lk[it];
            if ((kk & hmask) == prefix) atomicAdd(&hist[(kk >> sh) & 0xffu], 1u);
        }
        __syncthreads();
        // warp-parallel reverse scan over 256 bins (warp 0)
        if (wid == 0) {
            unsigned cnt[8];
            unsigned ssum = 0;
#pragma unroll
            for (int qq = 0; qq < 8; ++qq) { cnt[qq] = hist[lane * 8 + qq]; ssum += cnt[qq]; }
            unsigned x = ssum;
#pragma unroll
            for (int off = 1; off < 32; off <<= 1) {
                unsigned y = __shfl_down_sync(0xffffffffu, x, off);
                if (lane + off < 32) x += y;
            }
            unsigned excl = x - ssum;
            bool hit = (excl < remain) && (x >= remain);
            unsigned hmsk = __ballot_sync(0xffffffffu, hit);
            int hl = __ffs(hmsk) - 1;
            if (lane == hl) {
                unsigned cum = excl;
                int bq = 7;
                for (; bq > 0; --bq) {
                    if (cum + cnt[bq] >= remain) break;
                    cum += cnt[bq];
                }
                sh_bin = lane * 8 + bq;
                sh_cum = cum;
                sh_eq = cnt[bq];
            }
        }
        __syncthreads();
        prefix |= ((unsigned)sh_bin) << sh;
        hmask  |= 0xffu << sh;
        remain -= sh_cum;
        eqTotal = sh_eq;
        __syncthreads();
    }
    unsigned thresh = prefix;
    unsigned need = remain;

    // pass D: boolean output as float; p==0 forced true; p>=1 true iff
    // sampled index s=p-1 in top-k (index 8191 -> pos 8192 dropped).
#pragma unroll
    for (int it = 0; it < PER2; ++it) {
        int p = tid + it * NT2;
        float o;
        if (p == 0) {
            o = 1.0f;
        } else {
            int s = p - 1;
            unsigned kk = shv_u[s];
            if (kk > thresh) {
                o = 1.0f;
            } else if (kk == thresh) {
                if (eqTotal == need) {
                    o = 1.0f;
                } else {
                    unsigned rank = 0;
                    for (int j = 0; j < s; ++j) rank += (shv_u[j] == thresh);
                    o = (rank < need) ? 1.0f : 0.0f;
                }
            } else {
                o = 0.0f;
            }
        }
        out[bh * NS + p] = o;
    }
}

extern "C" void kernel_launch(void* const* d_in, const int* in_sizes, int n_in,
                              void* d_out, int out_size) {
    const float* q = (const float*)d_in[0];
    const float* k = (const float*)d_in[1];
    // d_in[2] = v : unused by the reference computation
    const float* token_mask = (const float*)d_in[3];

    init_kernel<<<1, 128>>>();
    score_kernel<<<SCTA, RT>>>(q, k);
    select_kernel<<<NBH, NT2>>>(token_mask, (float*)d_out);
}

// round 7
// speedup vs baseline: 1.7769x; 1.0600x over previous
#include <cuda_runtime.h>
#include <math.h>

#define NB 8
#define NH 12
#define NS 8192
#define ND 64
#define NBH (NB * NH)
#define KSEL 1024
#define NT2 1024
#define PER2 (NS / NT2)   // 8
#define RT 128            // rows per score tile
#define TILES_PER_CTA 8
#define CPB 8             // score CTAs per bh row
#define SCTA (NBH * CPB)  // 768

// device scratch (no allocs allowed)
__device__ float2 g_sg[NBH * NS];          // (score, gumbel) interleaved
__device__ unsigned g_maxpart[NBH * CPB];  // per-CTA encoded max, written every run

// ---------------- Threefry-2x32 (JAX), key = (0, 42) ----------------
__device__ __forceinline__ unsigned rotl32(unsigned x, int r) {
    return __funnelshift_l(x, x, r);
}

__device__ __forceinline__ void threefry2x32_0_42(unsigned c0, unsigned c1,
                                                  unsigned& o0, unsigned& o1) {
    const unsigned ks0 = 0u;
    const unsigned ks1 = 42u;
    const unsigned ks2 = 0x1BD11BDAu ^ 0u ^ 42u;
    unsigned x0 = c0 + ks0;
    unsigned x1 = c1 + ks1;
#define TF_R(r) { x0 += x1; x1 = rotl32(x1, (r)); x1 ^= x0; }
    TF_R(13) TF_R(15) TF_R(26) TF_R(6)
    x0 += ks1; x1 += ks2 + 1u;
    TF_R(17) TF_R(29) TF_R(16) TF_R(24)
    x0 += ks2; x1 += ks0 + 2u;
    TF_R(13) TF_R(15) TF_R(26) TF_R(6)
    x0 += ks0; x1 += ks1 + 3u;
    TF_R(17) TF_R(29) TF_R(16) TF_R(24)
    x0 += ks1; x1 += ks2 + 4u;
    TF_R(13) TF_R(15) TF_R(26) TF_R(6)
    x0 += ks2; x1 += ks0 + 5u;
#undef TF_R
    o0 = x0; o1 = x1;
}

// ---------------- accurate fp32 exp/log (fast-math immune, ~1 ulp) ----------------
__device__ __forceinline__ float f_exp(float x) {
    float n = rintf(x * 1.4426950408889634f);
    float r = __fmaf_rn(n, -0.693359375f, x);
    r = __fmaf_rn(n, 2.12194440e-4f, r);
    float p = 1.9841270e-4f;
    p = __fmaf_rn(p, r, 1.3888889e-3f);
    p = __fmaf_rn(p, r, 8.3333333e-3f);
    p = __fmaf_rn(p, r, 4.1666668e-2f);
    p = __fmaf_rn(p, r, 1.6666667e-1f);
    p = __fmaf_rn(p, r, 0.5f);
    float e = __fmaf_rn(p, r * r, r) + 1.0f;
    int ni = (int)n;
    ni = max(-126, min(127, ni));
    e *= __uint_as_float((unsigned)(ni + 127) << 23);
    return e;
}

__device__ __forceinline__ float f_log(float x) {
    unsigned u = __float_as_uint(x);
    int e = (int)(u >> 23) - 127;
    float m = __uint_as_float((u & 0x007fffffu) | 0x3f800000u);
    if (m > 1.4142135f) { m = m * 0.5f; e += 1; }
    float fe = (float)e;
    float s = __fdiv_rn(m - 1.0f, m + 1.0f);
    float s2 = s * s;
    float p = 0.11111111f;
    p = __fmaf_rn(p, s2, 0.14285715f);
    p = __fmaf_rn(p, s2, 0.2f);
    p = __fmaf_rn(p, s2, 0.33333334f);
    float w = s + s;
    float lm = __fmaf_rn(w * s2, p, w);
    float r = __fmaf_rn(fe, -2.12194440e-4f, lm);
    r = __fmaf_rn(fe, 0.693359375f, r);
    return r;
}

// ---------------- JAX gumbel(key=42) at flat index i ----------------
// PARTITIONABLE threefry: 32-bit draw = out0 ^ out1 of threefry(key, (0, i))
__device__ __forceinline__ float gumbel_at(unsigned i) {
    unsigned o0, o1;
    threefry2x32_0_42(0u, i, o0, o1);
    unsigned bits = o0 ^ o1;
    float f = __uint_as_float((bits >> 9) | 0x3f800000u) - 1.0f;   // [0,1)
    const float tiny = 1.17549435e-38f;
    float uu = f * (1.0f - tiny) + tiny;
    uu = fmaxf(tiny, uu);
    return -f_log(-f_log(uu));
}

// monotone float -> sortable uint (and inverse)
__device__ __forceinline__ unsigned f2k(float v) {
    unsigned u = __float_as_uint(v);
    return (u & 0x80000000u) ? ~u : (u | 0x80000000u);
}
__device__ __forceinline__ float k2f(unsigned k) {
    return (k & 0x80000000u) ? __uint_as_float(k & 0x7fffffffu)
                             : __uint_as_float(~k);
}

// ---------------- kernel 1: persistent scores + gumbel + per-CTA max ----------------
__global__ void __launch_bounds__(RT) score_kernel(const float* __restrict__ q,
                                                   const float* __restrict__ k) {
    __shared__ float4 sk[RT * 17];   // odd stride: conflict-free LDS.128
    __shared__ float4 qs4[16];
    __shared__ unsigned redmax[4];

    int t = threadIdx.x;
    int bh = blockIdx.x >> 3;                       // CPB=8 CTAs per bh
    int slot = blockIdx.x & 7;
    int row_base0 = slot * (TILES_PER_CTA * RT);    // 1024 rows per CTA

    if (t < 16)
        qs4[t] = ((const float4*)(q + (size_t)bh * NS * ND))[t];

    const float4* kg = (const float4*)(k + ((size_t)bh * NS + row_base0) * ND);

    // prologue: prefetch tile 0 into registers
    float4 stage[16];
#pragma unroll
    for (int i = 0; i < 16; ++i) stage[i] = kg[i * RT + t];

    float cmax = -3.402823466e38f;

    for (int it = 0; it < TILES_PER_CTA; ++it) {
        // commit staged tile to smem
#pragma unroll
        for (int i = 0; i < 16; ++i) {
            int L = i * RT + t;
            sk[(L >> 4) * 17 + (L & 15)] = stage[i];
        }
        __syncthreads();

        // prefetch next tile (LDGs in flight while we compute)
        if (it + 1 < TILES_PER_CTA) {
            const float4* kgn = kg + (it + 1) * (RT * 16);
#pragma unroll
            for (int i = 0; i < 16; ++i) stage[i] = kgn[i * RT + t];
        }

        // compute this tile: thread t owns row (row_base0 + it*RT + t)
        float4 acc = make_float4(0.f, 0.f, 0.f, 0.f);
#pragma unroll
        for (int j = 0; j < 16; ++j) {
            float4 kv = sk[t * 17 + j];
            float4 qv = qs4[j];
            acc.x = __fmaf_rn(qv.x, kv.x, acc.x);
            acc.y = __fmaf_rn(qv.y, kv.y, acc.y);
            acc.z = __fmaf_rn(qv.z, kv.z, acc.z);
            acc.w = __fmaf_rn(qv.w, kv.w, acc.w);
        }
        float dot = ((acc.x + acc.y) + (acc.z + acc.w)) * 0.125f;
        int flat = bh * NS + row_base0 + it * RT + t;
        cmax = fmaxf(cmax, dot);
        g_sg[flat] = make_float2(dot, gumbel_at((unsigned)flat));  // one STG.64

        __syncthreads();   // all reads of sk done before next overwrite
    }

    // CTA max -> dedicated slot (no reset, no atomics; exact & deterministic)
    for (int o = 16; o; o >>= 1) cmax = fmaxf(cmax, __shfl_xor_sync(0xffffffffu, cmax, o));
    if ((t & 31) == 0) redmax[t >> 5] = f2k(cmax);
    __syncthreads();
    if (t == 0) {
        unsigned m = redmax[0];
        m = max(m, redmax[1]); m = max(m, redmax[2]); m = max(m, redmax[3]);
        g_maxpart[bh * CPB + slot] = m;
    }
}

// ---------------- kernel 2: softmax probs + gumbel add + radix top-k + scatter ----------------
__global__ void __launch_bounds__(NT2) select_kernel(const float* __restrict__ token_mask,
                                                     float* __restrict__ out) {
    int bh = blockIdx.x;
    int b = bh / NH;
    int tid = threadIdx.x;
    int lane = tid & 31, wid = tid >> 5;

    __shared__ float shv_f[NS];          // 32 KB, sortable keys
    __shared__ unsigned hist[256];
    __shared__ double red_d[32];
    __shared__ float sh_denom;
    __shared__ int sh_bin;
    __shared__ unsigned sh_cum, sh_eq;
    unsigned* shv_u = (unsigned*)shv_f;

    const float2* sg = g_sg + bh * NS;

    // exact row max from the 8 per-CTA slots
    unsigned me = g_maxpart[bh * CPB + 0];
#pragma unroll
    for (int i = 1; i < CPB; ++i) me = max(me, g_maxpart[bh * CPB + i]);
    float mx = k2f(me);

    // pass A/B fused: e = exp(score - max) * mask; double sum (rounded once)
    float le[PER2];
    float lg[PER2];
    double lsum = 0.0;
#pragma unroll
    for (int it = 0; it < PER2; ++it) {
        int s = tid + it * NT2;
        float2 v = sg[s];                 // one LDG.64
        float e = f_exp(v.x - mx) * token_mask[b * NS + s];
        le[it] = e;
        lg[it] = v.y;
        lsum += (double)e;
    }
    for (int o = 16; o; o >>= 1) lsum += __shfl_xor_sync(0xffffffffu, lsum, o);
    if (lane == 0) red_d[wid] = lsum;
    __syncthreads();
    if (wid == 0) {
        double tt = red_d[lane];
        for (int o = 16; o; o >>= 1) tt += __shfl_xor_sync(0xffffffffu, tt, o);
        if (lane == 0) sh_denom = (float)tt + 1e-6f;
    }
    __syncthreads();
    float denom = sh_denom;

    // pass C: value = log((e + eps/S)/denom) + gumbel ; sortable keys
    const float C1 = (float)(1e-6 / 8192.0);
    unsigned lk[PER2];
#pragma unroll
    for (int it = 0; it < PER2; ++it) {
        int s = tid + it * NT2;
        float att = __fdiv_rn(__fadd_rn(le[it], C1), denom);
        float v = __fadd_rn(f_log(att), lg[it]);
        unsigned kk = f2k(v);
        lk[it] = kk;
        shv_u[s] = kk;
    }
    __syncthreads();

    // radix select: threshold key of the KSEL-th largest (ties -> lowest index)
    unsigned prefix = 0, hmask = 0, remain = KSEL, eqTotal = 0;
    for (int byte = 3; byte >= 0; --byte) {
        if (tid < 256) hist[tid] = 0;
        __syncthreads();
        int sh = byte * 8;
#pragma unroll
        for (int it = 0; it < PER2; ++it) {
            unsigned kk = lk[it];
            if ((kk & hmask) == prefix) atomicAdd(&hist[(kk >> sh) & 0xffu], 1u);
        }
        __syncthreads();
        // warp-parallel reverse scan over 256 bins (warp 0)
        if (wid == 0) {
            unsigned cnt[8];
            unsigned ssum = 0;
#pragma unroll
            for (int qq = 0; qq < 8; ++qq) { cnt[qq] = hist[lane * 8 + qq]; ssum += cnt[qq]; }
            unsigned x = ssum;
#pragma unroll
            for (int off = 1; off < 32; off <<= 1) {
                unsigned y = __shfl_down_sync(0xffffffffu, x, off);
                if (lane + off < 32) x += y;
            }
            unsigned excl = x - ssum;
            bool hit = (excl < remain) && (x >= remain);
            unsigned hmsk = __ballot_sync(0xffffffffu, hit);
            int hl = __ffs(hmsk) - 1;
            if (lane == hl) {
                unsigned cum = excl;
                int bq = 7;
                for (; bq > 0; --bq) {
                    if (cum + cnt[bq] >= remain) break;
                    cum += cnt[bq];
                }
                sh_bin = lane * 8 + bq;
                sh_cum = cum;
                sh_eq = cnt[bq];
            }
        }
        __syncthreads();
        prefix |= ((unsigned)sh_bin) << sh;
        hmask  |= 0xffu << sh;
        remain -= sh_cum;
        eqTotal = sh_eq;
        __syncthreads();
    }
    unsigned thresh = prefix;
    unsigned need = remain;

    // pass D: boolean output as float; p==0 forced true; p>=1 true iff
    // sampled index s=p-1 in top-k (index 8191 -> pos 8192 dropped).
#pragma unroll
    for (int it = 0; it < PER2; ++it) {
        int p = tid + it * NT2;
        float o;
        if (p == 0) {
            o = 1.0f;
        } else {
            int s = p - 1;
            unsigned kk = shv_u[s];
            if (kk > thresh) {
                o = 1.0f;
            } else if (kk == thresh) {
                if (eqTotal == need) {
                    o = 1.0f;
                } else {
                    unsigned rank = 0;
                    for (int j = 0; j < s; ++j) rank += (shv_u[j] == thresh);
                    o = (rank < need) ? 1.0f : 0.0f;
                }
            } else {
                o = 0.0f;
            }
        }
        out[bh * NS + p] = o;
    }
}

extern "C" void kernel_launch(void* const* d_in, const int* in_sizes, int n_in,
                              void* d_out, int out_size) {
    const float* q = (const float*)d_in[0];
    const float* k = (const float*)d_in[1];
    // d_in[2] = v : unused by the reference computation
    const float* token_mask = (const float*)d_in[3];

    score_kernel<<<SCTA, RT>>>(q, k);
    select_kernel<<<NBH, NT2>>>(token_mask, (float*)d_out);
}

// round 8
// speedup vs baseline: 1.8679x; 1.0512x over previous
#include <cuda_runtime.h>
#include <math.h>

#define NB 8
#define NH 12
#define NS 8192
#define ND 64
#define NBH (NB * NH)
#define KSEL 1024
#define NT2 1024
#define PER2 (NS / NT2)   // 8

#define NSM 152           // GB300 SM count
#define SRT 256           // score threads per CTA
#define TROWS 256         // rows per score tile
#define NTILES (NBH * NS / TROWS)        // 3072
#define TPB (NS / TROWS)                 // 32 tiles per bh
#define SK_F4 (TROWS * 17)               // float4 per buffer (with pad)
#define DYN_SMEM ((2 * SK_F4 + 32) * 16) // 2 buffers + q[2][16]

// device scratch (no allocs allowed)
__device__ float2 g_sg[NBH * NS];        // (score, gumbel) interleaved
__device__ unsigned g_maxpart[NTILES];   // per-tile encoded max, written every run

// ---------------- Threefry-2x32 (JAX), key = (0, 42) ----------------
__device__ __forceinline__ unsigned rotl32(unsigned x, int r) {
    return __funnelshift_l(x, x, r);
}

__device__ __forceinline__ void threefry2x32_0_42(unsigned c0, unsigned c1,
                                                  unsigned& o0, unsigned& o1) {
    const unsigned ks0 = 0u;
    const unsigned ks1 = 42u;
    const unsigned ks2 = 0x1BD11BDAu ^ 0u ^ 42u;
    unsigned x0 = c0 + ks0;
    unsigned x1 = c1 + ks1;
#define TF_R(r) { x0 += x1; x1 = rotl32(x1, (r)); x1 ^= x0; }
    TF_R(13) TF_R(15) TF_R(26) TF_R(6)
    x0 += ks1; x1 += ks2 + 1u;
    TF_R(17) TF_R(29) TF_R(16) TF_R(24)
    x0 += ks2; x1 += ks0 + 2u;
    TF_R(13) TF_R(15) TF_R(26) TF_R(6)
    x0 += ks0; x1 += ks1 + 3u;
    TF_R(17) TF_R(29) TF_R(16) TF_R(24)
    x0 += ks1; x1 += ks2 + 4u;
    TF_R(13) TF_R(15) TF_R(26) TF_R(6)
    x0 += ks2; x1 += ks0 + 5u;
#undef TF_R
    o0 = x0; o1 = x1;
}

// ---------------- accurate fp32 exp/log (fast-math immune, ~1 ulp) ----------------
__device__ __forceinline__ float f_exp(float x) {
    float n = rintf(x * 1.4426950408889634f);
    float r = __fmaf_rn(n, -0.693359375f, x);
    r = __fmaf_rn(n, 2.12194440e-4f, r);
    float p = 1.9841270e-4f;
    p = __fmaf_rn(p, r, 1.3888889e-3f);
    p = __fmaf_rn(p, r, 8.3333333e-3f);
    p = __fmaf_rn(p, r, 4.1666668e-2f);
    p = __fmaf_rn(p, r, 1.6666667e-1f);
    p = __fmaf_rn(p, r, 0.5f);
    float e = __fmaf_rn(p, r * r, r) + 1.0f;
    int ni = (int)n;
    ni = max(-126, min(127, ni));
    e *= __uint_as_float((unsigned)(ni + 127) << 23);
    return e;
}

__device__ __forceinline__ float f_log(float x) {
    unsigned u = __float_as_uint(x);
    int e = (int)(u >> 23) - 127;
    float m = __uint_as_float((u & 0x007fffffu) | 0x3f800000u);
    if (m > 1.4142135f) { m = m * 0.5f; e += 1; }
    float fe = (float)e;
    float s = __fdiv_rn(m - 1.0f, m + 1.0f);
    float s2 = s * s;
    float p = 0.11111111f;
    p = __fmaf_rn(p, s2, 0.14285715f);
    p = __fmaf_rn(p, s2, 0.2f);
    p = __fmaf_rn(p, s2, 0.33333334f);
    float w = s + s;
    float lm = __fmaf_rn(w * s2, p, w);
    float r = __fmaf_rn(fe, -2.12194440e-4f, lm);
    r = __fmaf_rn(fe, 0.693359375f, r);
    return r;
}

// ---------------- JAX gumbel(key=42) at flat index i ----------------
__device__ __forceinline__ float gumbel_at(unsigned i) {
    unsigned o0, o1;
    threefry2x32_0_42(0u, i, o0, o1);
    unsigned bits = o0 ^ o1;
    float f = __uint_as_float((bits >> 9) | 0x3f800000u) - 1.0f;   // [0,1)
    const float tiny = 1.17549435e-38f;
    float uu = f * (1.0f - tiny) + tiny;
    uu = fmaxf(tiny, uu);
    return -f_log(-f_log(uu));
}

// monotone float -> sortable uint (and inverse)
__device__ __forceinline__ unsigned f2k(float v) {
    unsigned u = __float_as_uint(v);
    return (u & 0x80000000u) ? ~u : (u | 0x80000000u);
}
__device__ __forceinline__ float k2f(unsigned k) {
    return (k & 0x80000000u) ? __uint_as_float(k & 0x7fffffffu)
                             : __uint_as_float(~k);
}

__device__ __forceinline__ void cp16(float4* dst_smem, const float4* src) {
    unsigned d = (unsigned)__cvta_generic_to_shared(dst_smem);
    asm volatile("cp.async.cg.shared.global [%0], [%1], 16;" :: "r"(d), "l"(src));
}

// ---------------- kernel 1: persistent streaming scores + gumbel + per-tile max ----------------
__global__ void __launch_bounds__(SRT) score_kernel(const float* __restrict__ q,
                                                    const float* __restrict__ k) {
    extern __shared__ float4 dsm[];
    float4* skbuf = dsm;                 // [2][SK_F4]
    float4* qb = dsm + 2 * SK_F4;        // [2][16]
    __shared__ unsigned redmax[8];

    int c = blockIdx.x;
    int t = threadIdx.x;
    // contiguous tile runs: 3072 = 152*20 + 32 -> CTAs 0..31 get 21 tiles
    int start = (c < 32) ? c * 21 : 20 * c + 32;
    int len = (c < 32) ? 21 : 20;

    const float4* k4 = (const float4*)k;

    // prologue: prefetch tiles start, start+1 (+ their q rows)
#pragma unroll
    for (int pn = 0; pn < 2; ++pn) {
        int tile = start + pn;
        float4* buf = skbuf + pn * SK_F4;
        if (t < 16) {
            int bh = tile / TPB;
            qb[pn * 16 + t] = ((const float4*)(q + (size_t)bh * NS * ND))[t];
        }
        const float4* kg = k4 + (size_t)tile * (TROWS * 16);
#pragma unroll
        for (int i = 0; i < 16; ++i) {
            int L = i * SRT + t;
            cp16(&buf[(L >> 4) * 17 + (L & 15)], kg + L);
        }
        asm volatile("cp.async.commit_group;" ::: "memory");
    }

    for (int n = 0; n < len; ++n) {
        int tile = start + n;
        int slot = n & 1;
        float4* buf = skbuf + slot * SK_F4;

        if (n + 1 < len) {
            asm volatile("cp.async.wait_group 1;" ::: "memory");
        } else {
            asm volatile("cp.async.wait_group 0;" ::: "memory");
        }
        __syncthreads();

        // compute: thread t owns row (tile*TROWS + t); q broadcast from qb[slot]
        float4 acc = make_float4(0.f, 0.f, 0.f, 0.f);
#pragma unroll
        for (int j = 0; j < 16; ++j) {
            float4 kv = buf[t * 17 + j];
            float4 qv = qb[slot * 16 + j];
            acc.x = __fmaf_rn(qv.x, kv.x, acc.x);
            acc.y = __fmaf_rn(qv.y, kv.y, acc.y);
            acc.z = __fmaf_rn(qv.z, kv.z, acc.z);
            acc.w = __fmaf_rn(qv.w, kv.w, acc.w);
        }
        float dot = ((acc.x + acc.y) + (acc.z + acc.w)) * 0.125f;
        unsigned flat = (unsigned)tile * TROWS + t;     // == bh*NS + s
        g_sg[flat] = make_float2(dot, gumbel_at(flat));

        // per-tile max (exact, order-free)
        float cmax = dot;
        for (int o = 16; o; o >>= 1) cmax = fmaxf(cmax, __shfl_xor_sync(0xffffffffu, cmax, o));
        if ((t & 31) == 0) redmax[t >> 5] = f2k(cmax);
        __syncthreads();   // redmax ready AND all buf/qb reads complete
        if (t == 0) {
            unsigned m = redmax[0];
#pragma unroll
            for (int i = 1; i < 8; ++i) m = max(m, redmax[i]);
            g_maxpart[tile] = m;
        }

        // prefetch tile n+2 into this (now free) buffer
        if (n + 2 < len) {
            int tile2 = start + n + 2;
            if (t < 16) {
                int bh2 = tile2 / TPB;
                qb[slot * 16 + t] = ((const float4*)(q + (size_t)bh2 * NS * ND))[t];
            }
            const float4* kg2 = k4 + (size_t)tile2 * (TROWS * 16);
#pragma unroll
            for (int i = 0; i < 16; ++i) {
                int L = i * SRT + t;
                cp16(&buf[(L >> 4) * 17 + (L & 15)], kg2 + L);
            }
            asm volatile("cp.async.commit_group;" ::: "memory");
        }
    }
}

// ---------------- kernel 2: softmax probs + gumbel add + radix top-k + scatter ----------------
__global__ void __launch_bounds__(NT2) select_kernel(const float* __restrict__ token_mask,
                                                     float* __restrict__ out) {
    int bh = blockIdx.x;
    int b = bh / NH;
    int tid = threadIdx.x;
    int lane = tid & 31, wid = tid >> 5;

    __shared__ float shv_f[NS];          // 32 KB, sortable keys
    __shared__ unsigned hist[256];
    __shared__ double red_d[32];
    __shared__ unsigned sh_maxe;
    __shared__ float sh_denom;
    __shared__ int sh_bin;
    __shared__ unsigned sh_cum, sh_eq;
    unsigned* shv_u = (unsigned*)shv_f;

    const float2* sg = g_sg + bh * NS;

    // exact row max from the 32 per-tile slots (warp 0)
    if (wid == 0) {
        unsigned me = g_maxpart[bh * TPB + lane];
        for (int o = 16; o; o >>= 1) me = max(me, __shfl_xor_sync(0xffffffffu, me, o));
        if (lane == 0) sh_maxe = me;
    }
    __syncthreads();
    float mx = k2f(sh_maxe);

    // pass A/B fused: e = exp(score - max) * mask; double sum (rounded once)
    float le[PER2];
    float lg[PER2];
    double lsum = 0.0;
#pragma unroll
    for (int it = 0; it < PER2; ++it) {
        int s = tid + it * NT2;
        float2 v = sg[s];                 // one LDG.64
        float e = f_exp(v.x - mx) * token_mask[b * NS + s];
        le[it] = e;
        lg[it] = v.y;
        lsum += (double)e;
    }
    for (int o = 16; o; o >>= 1) lsum += __shfl_xor_sync(0xffffffffu, lsum, o);
    if (lane == 0) red_d[wid] = lsum;
    __syncthreads();
    if (wid == 0) {
        double tt = red_d[lane];
        for (int o = 16; o; o >>= 1) tt += __shfl_xor_sync(0xffffffffu, tt, o);
        if (lane == 0) sh_denom = (float)tt + 1e-6f;
    }
    __syncthreads();
    float denom = sh_denom;

    // pass C: value = log((e + eps/S)/denom) + gumbel ; sortable keys
    const float C1 = (float)(1e-6 / 8192.0);
    unsigned lk[PER2];
#pragma unroll
    for (int it = 0; it < PER2; ++it) {
        int s = tid + it * NT2;
        float att = __fdiv_rn(__fadd_rn(le[it], C1), denom);
        float v = __fadd_rn(f_log(att), lg[it]);
        unsigned kk = f2k(v);
        lk[it] = kk;
        shv_u[s] = kk;
    }
    __syncthreads();

    // radix select: threshold key of the KSEL-th largest (ties -> lowest index)
    unsigned prefix = 0, hmask = 0, remain = KSEL, eqTotal = 0;
    for (int byte = 3; byte >= 0; --byte) {
        if (tid < 256) hist[tid] = 0;
        __syncthreads();
        int sh = byte * 8;
#pragma unroll
        for (int it = 0; it < PER2; ++it) {
            unsigned kk = lk[it];
            if ((kk & hmask) == prefix) atomicAdd(&hist[(kk >> sh) & 0xffu], 1u);
        }
        __syncthreads();
        // warp-parallel reverse scan over 256 bins (warp 0)
        if (wid == 0) {
            unsigned cnt[8];
            unsigned ssum = 0;
#pragma unroll
            for (int qq = 0; qq < 8; ++qq) { cnt[qq] = hist[lane * 8 + qq]; ssum += cnt[qq]; }
            unsigned x = ssum;
#pragma unroll
            for (int off = 1; off < 32; off <<= 1) {
                unsigned y = __shfl_down_sync(0xffffffffu, x, off);
                if (lane + off < 32) x += y;
            }
            unsigned excl = x - ssum;
            bool hit = (excl < remain) && (x >= remain);
            unsigned hmsk = __ballot_sync(0xffffffffu, hit);
            int hl = __ffs(hmsk) - 1;
            if (lane == hl) {
                unsigned cum = excl;
                int bq = 7;
                for (; bq > 0; --bq) {
                    if (cum + cnt[bq] >= remain) break;
                    cum += cnt[bq];
                }
                sh_bin = lane * 8 + bq;
                sh_cum = cum;
                sh_eq = cnt[bq];
            }
        }
        __syncthreads();
        prefix |= ((unsigned)sh_bin) << sh;
        hmask  |= 0xffu << sh;
        remain -= sh_cum;
        eqTotal = sh_eq;
        __syncthreads();
    }
    unsigned thresh = prefix;
    unsigned need = remain;

    // pass D: boolean output as float; p==0 forced true; p>=1 true iff
    // sampled index s=p-1 in top-k (index 8191 -> pos 8192 dropped).
#pragma unroll
    for (int it = 0; it < PER2; ++it) {
        int p = tid + it * NT2;
        float o;
        if (p == 0) {
            o = 1.0f;
        } else {
            int s = p - 1;
            unsigned kk = shv_u[s];
            if (kk > thresh) {
                o = 1.0f;
            } else if (kk == thresh) {
                if (eqTotal == need) {
                    o = 1.0f;
                } else {
                    unsigned rank = 0;
                    for (int j = 0; j < s; ++j) rank += (shv_u[j] == thresh);
                    o = (rank < need) ? 1.0f : 0.0f;
                }
            } else {
                o = 0.0f;
            }
        }
        out[bh * NS + p] = o;
    }
}

extern "C" void kernel_launch(void* const* d_in, const int* in_sizes, int n_in,
                              void* d_out, int out_size) {
    const float* q = (const float*)d_in[0];
    const float* k = (const float*)d_in[1];
    // d_in[2] = v : unused by the reference computation
    const float* token_mask = (const float*)d_in[3];

    cudaFuncSetAttribute(score_kernel, cudaFuncAttributeMaxDynamicSharedMemorySize, DYN_SMEM);
    score_kernel<<<NSM, SRT, DYN_SMEM>>>(q, k);
    select_kernel<<<NBH, NT2>>>(token_mask, (float*)d_out);
}